// round 7
// baseline (speedup 1.0000x reference)
#include <cuda_runtime.h>

#define H 512
#define W 512
#define C 3
#define HW (H * W)
#define CHW (C * H * W)
#define N_IT 30

static constexpr float TAU      = (float)0.01;
static constexpr float LAM2     = (float)0.15;
static constexpr float RHO      = (float)1.99;
static constexpr float SIGMA    = (float)(1.0 / 0.01 / 72.0);
static constexpr float TAU_LAM1 = (float)(0.01 * 0.1);
static constexpr float INV_1PT  = (float)(1.0 / 1.01);

static constexpr int TILE   = 32;
static constexpr int SU_DIM = 40, SU_N = SU_DIM * SU_DIM;   // u patch, halo 4
static constexpr int ST_DIM = 38, ST_N = ST_DIM * ST_DIM;   // tmp, halo 3
static constexpr int SPX_DIM = 36, SPX_N = SPX_DIM * SPX_DIM; // px, halo 2
static constexpr int SP_DIM = 34, SP_N = SP_DIM * SP_DIM;   // p0/p1/q, halo 1
static constexpr int SMEM_FLOATS = 4 * SU_N + 2 * ST_N + SPX_N + 2 * SP_N; // 12896
static constexpr int SMEM_BYTES  = SMEM_FLOATS * 4;                        // 51584

// Ping-pong state planes (static device arrays — no cudaMalloc anywhere)
__device__ float g_x2[2][CHW];
__device__ float g_r0[2][CHW], g_r1[2][CHW];
__device__ float g_u0[2][CHW], g_u1[2][CHW], g_u2[2][CHW], g_u3[2][CHW];

__device__ __forceinline__ float4 ld4(const float* p) {
    return *reinterpret_cast<const float4*>(p);
}
__device__ __forceinline__ void st4(float* p, float a, float b, float c, float d) {
    *reinterpret_cast<float4*>(p) = make_float4(a, b, c, d);
}

// ---------------------------------------------------------------------------
// Init buffer 0: x2 = y, r = 0, u = 0
// ---------------------------------------------------------------------------
__global__ __launch_bounds__(256) void k_init(const float* __restrict__ y) {
    int t = blockIdx.x * blockDim.x + threadIdx.x;
    int idx = t * 4;
    *reinterpret_cast<float4*>(g_x2[0] + idx) = ld4(y + idx);
    st4(g_r0[0] + idx, 0.f, 0.f, 0.f, 0.f);
    st4(g_r1[0] + idx, 0.f, 0.f, 0.f, 0.f);
    st4(g_u0[0] + idx, 0.f, 0.f, 0.f, 0.f);
    st4(g_u1[0] + idx, 0.f, 0.f, 0.f, 0.f);
    st4(g_u2[0] + idx, 0.f, 0.f, 0.f, 0.f);
    st4(g_u3[0] + idx, 0.f, 0.f, 0.f, 0.f);
}

// ---------------------------------------------------------------------------
// One full TGV iteration per launch. 32x32 output tile per block; all
// intermediates (tmp, px, p0/p1, q) live in shared memory with halo
// recompute. State is ping-pong (src -> src^1); last iteration writes the
// d_out tuple layout (x2 plane | r2 AoS pairs | u2 AoS float4) instead.
// ---------------------------------------------------------------------------
__global__ __launch_bounds__(256) void k_iter(int src, int last,
                                              float* __restrict__ out,
                                              const float* __restrict__ y) {
    extern __shared__ float sm[];
    float* su0 = sm;
    float* su1 = su0 + SU_N;
    float* su2 = su1 + SU_N;
    float* su3 = su2 + SU_N;
    float* st0 = su3 + SU_N;
    float* st1 = st0 + ST_N;
    float* spx = st1 + ST_N;
    float* sp0 = spx + SPX_N;
    float* sp1 = sp0 + SP_N;
    float* q0s = st0;   // alias: tmp dead once px/p0/p1 are built
    float* q1s = st1;

    const int tid = threadIdx.x;
    const int bid = blockIdx.x;
    const int c   = bid >> 8;                 // 256 tiles per channel
    const int rem = bid & 255;
    const int gi0 = (rem >> 4) * TILE;
    const int gj0 = (rem & 15) * TILE;
    const int base = c * HW;
    const int dst = src ^ 1;

    const float* __restrict__ x2i = g_x2[src];
    const float* __restrict__ r0i = g_r0[src];
    const float* __restrict__ r1i = g_r1[src];
    const float* __restrict__ u0i = g_u0[src];
    const float* __restrict__ u1i = g_u1[src];
    const float* __restrict__ u2i = g_u2[src];
    const float* __restrict__ u3i = g_u3[src];
    float* __restrict__ x2o = g_x2[dst];
    float* __restrict__ r0o = g_r0[dst];
    float* __restrict__ r1o = g_r1[dst];
    float* __restrict__ u0o = g_u0[dst];
    float* __restrict__ u1o = g_u1[dst];
    float* __restrict__ u2o = g_u2[dst];
    float* __restrict__ u3o = g_u3[dst];

#if __CUDA_ARCH__ >= 900
    cudaGridDependencySynchronize();
#endif

    // ---- S0: load u patches (halo 4), zero-filled outside image ----------
    for (int idx = tid; idx < SU_N; idx += 256) {
        int li = idx / SU_DIM, lj = idx - li * SU_DIM;
        int gi = gi0 - 4 + li, gj = gj0 - 4 + lj;
        bool in = ((unsigned)gi < H) && ((unsigned)gj < W);
        int g = base + gi * W + gj;
        su0[idx] = in ? u0i[g] : 0.f;
        su1[idx] = in ? u1i[g] : 0.f;
        su2[idx] = in ? u2i[g] : 0.f;
        su3[idx] = in ? u3i[g] : 0.f;
    }
    __syncthreads();

    // ---- S1: tmp = TAU * epsilonT(u) on halo-3 region --------------------
    for (int idx = tid; idx < ST_N; idx += 256) {
        int li = idx / ST_DIM, lj = idx - li * ST_DIM;
        int oi = li - 3, oj = lj - 3;
        int gi = gi0 + oi, gj = gj0 + oj;
        bool up = gi >= 1, down = gi + 1 < H, left = gj >= 1, right = gj + 1 < W;
        int cu = (oi + 4) * SU_DIM + (oj + 4);
        float t0 = TAU * (su0[cu] - (down ? su0[cu + SU_DIM] : 0.f)
                          + (left ? su1[cu] : 0.f) - (right ? su1[cu + 1] : 0.f));
        float t1 = TAU * (su2[cu] - (right ? su2[cu + 1] : 0.f)
                          + (up ? su3[cu - SU_DIM] : 0.f) - (down ? su3[cu] : 0.f));
        st0[idx] = t0;
        st1[idx] = t1;
    }
    __syncthreads();

    // ---- S2: x / px on halo-2 region; x2 state write at center -----------
    for (int idx = tid; idx < SPX_N; idx += 256) {
        int li = idx / SPX_DIM, lj = idx - li * SPX_DIM;
        int oi = li - 2, oj = lj - 2;
        int gi = gi0 + oi, gj = gj0 + oj;
        bool up = gi >= 1, down = gi + 1 < H, left = gj >= 1, right = gj + 1 < W;
        int ct = (oi + 3) * ST_DIM + (oj + 3);
        float dv = (up ? st0[ct - ST_DIM] : 0.f) - (down ? st0[ct] : 0.f)
                 + (left ? st1[ct - 1] : 0.f) - (right ? st1[ct] : 0.f);
        bool in = ((unsigned)gi < H) && ((unsigned)gj < W);
        int g = base + gi * W + gj;
        float x2old = in ? x2i[g] : 0.f;
        float yv    = in ? y[g]   : 0.f;
        float x = (x2old - dv + TAU * yv) * INV_1PT;
        spx[idx] = 2.0f * x - x2old;
        if ((unsigned)oi < TILE && (unsigned)oj < TILE) {
            float xn = x2old + RHO * (x - x2old);
            if (last) out[g] = xn;
            else      x2o[g] = xn;
        }
    }

    // ---- S3: r / p0 / p1 on halo-1 region; r2 state write at center ------
    // (no barrier needed between S2 and S3: S3 reads st*, not spx)
    for (int idx = tid; idx < SP_N; idx += 256) {
        int li = idx / SP_DIM, lj = idx - li * SP_DIM;
        int oi = li - 1, oj = lj - 1;
        int gi = gi0 + oi, gj = gj0 + oj;
        bool in = ((unsigned)gi < H) && ((unsigned)gj < W);
        int ct = (oi + 3) * ST_DIM + (oj + 3);
        float t0 = st0[ct], t1 = st1[ct];
        int g = base + gi * W + gj;
        float r0old = in ? r0i[g] : 0.f;
        float r1old = in ? r1i[g] : 0.f;
        float rr0 = r0old + t0;
        float rr1 = r1old + t1;
        float s  = rr0 * rr0 + rr1 * rr1;
        float im = fminf(TAU_LAM1 * rsqrtf(s), 1.0f);
        float r0 = rr0 - rr0 * im;
        float r1 = rr1 - rr1 * im;
        sp0[idx] = 2.0f * r0 - r0old;
        sp1[idx] = 2.0f * r1 - r1old;
        if ((unsigned)oi < TILE && (unsigned)oj < TILE) {
            float rn0 = r0old + RHO * (r0 - r0old);
            float rn1 = r1old + RHO * (r1 - r1old);
            if (last) { out[CHW + 2 * g] = rn0; out[CHW + 2 * g + 1] = rn1; }
            else      { r0o[g] = rn0; r1o[g] = rn1; }
        }
    }
    __syncthreads();

    // ---- S4: q = nabla(px) - pr on halo-1 region (writes alias st*) ------
    for (int idx = tid; idx < SP_N; idx += 256) {
        int li = idx / SP_DIM, lj = idx - li * SP_DIM;
        int oi = li - 1, oj = lj - 1;
        int gi = gi0 + oi, gj = gj0 + oj;
        bool down = gi + 1 < H, right = gj + 1 < W;
        int cp = (oi + 2) * SPX_DIM + (oj + 2);
        float pc = spx[cp];
        float q0 = (down  ? (spx[cp + SPX_DIM] - pc) : 0.f) - sp0[idx];
        float q1 = (right ? (spx[cp + 1]       - pc) : 0.f) - sp1[idx];
        q0s[idx] = q0;
        q1s[idx] = q1;
    }
    __syncthreads();

    // ---- S5: e = epsilon(q); u prox + over-relax; write u state ----------
    for (int idx = tid; idx < TILE * TILE; idx += 256) {
        int oi = idx / TILE, oj = idx - oi * TILE;
        int gi = gi0 + oi, gj = gj0 + oj;
        bool up = gi >= 1, down = gi + 1 < H, left = gj >= 1;
        int cq = (oi + 1) * SP_DIM + (oj + 1);
        float e0 = q0s[cq] - (up ? q0s[cq - SP_DIM] : 0.f);
        float e1 = left ? (q0s[cq] - q0s[cq - 1]) : 0.f;
        float e2 = q1s[cq] - (left ? q1s[cq - 1] : 0.f);
        float e3 = down ? (q1s[cq + SP_DIM] - q1s[cq]) : 0.f;

        int cu = (oi + 4) * SU_DIM + (oj + 4);
        float uo0 = su0[cu], uo1 = su1[cu], uo2 = su2[cu], uo3 = su3[cu];
        float un0 = uo0 + SIGMA * e0;
        float un1 = uo1 + SIGMA * e1;
        float un2 = uo2 + SIGMA * e2;
        float un3 = uo3 + SIGMA * e3;
        float s  = un0 * un0 + un1 * un1 + un2 * un2 + un3 * un3;
        float im = fminf(LAM2 * rsqrtf(s), 1.0f);
        float nu0 = uo0 + RHO * (un0 * im - uo0);
        float nu1 = uo1 + RHO * (un1 * im - uo1);
        float nu2 = uo2 + RHO * (un2 * im - uo2);
        float nu3 = uo3 + RHO * (un3 * im - uo3);

        int g = base + gi * W + gj;
        if (last) {
            reinterpret_cast<float4*>(out + 3 * CHW)[g] =
                make_float4(nu0, nu1, nu2, nu3);
        } else {
            u0o[g] = nu0; u1o[g] = nu1; u2o[g] = nu2; u3o[g] = nu3;
        }
    }
}

// ---------------------------------------------------------------------------
// Host: init + 30 fused iterations with PDL. n_it_max fixed to 30.
// ---------------------------------------------------------------------------
extern "C" void kernel_launch(void* const* d_in, const int* in_sizes, int n_in,
                              void* d_out, int out_size) {
    const float* y = (const float*)d_in[0];
    float* out = (float*)d_out;

    cudaFuncSetAttribute(k_iter, cudaFuncAttributeMaxDynamicSharedMemorySize,
                         SMEM_BYTES);

    k_init<<<CHW / 4 / 256, 256>>>(y);

    for (int it = 0; it < N_IT; ++it) {
        cudaLaunchConfig_t cfg = {};
        cfg.gridDim  = dim3(768);    // 16x16 tiles x 3 channels
        cfg.blockDim = dim3(256);
        cfg.dynamicSmemBytes = SMEM_BYTES;
        cfg.stream = 0;
        cudaLaunchAttribute attr[1];
        attr[0].id = cudaLaunchAttributeProgrammaticStreamSerialization;
        attr[0].val.programmaticStreamSerializationAllowed = 1;
        cfg.attrs = attr;
        cfg.numAttrs = 1;
        cudaLaunchKernelEx(&cfg, k_iter, it & 1, (it == N_IT - 1) ? 1 : 0,
                           out, y);
    }
}

// round 8
// speedup vs baseline: 1.9866x; 1.9866x over previous
#include <cuda_runtime.h>

#define H 512
#define W 512
#define C 3
#define HW (H * W)
#define CHW (C * H * W)
#define N_IT 30

static constexpr float TAU      = (float)0.01;
static constexpr float LAM2     = (float)0.15;
static constexpr float RHO      = (float)1.99;
static constexpr float SIGMA    = (float)(1.0 / 0.01 / 72.0);
static constexpr float TAU_LAM1 = (float)(0.01 * 0.1);
static constexpr float INV_1PT  = (float)(1.0 / 1.01);

// SoA scratch planes (static device arrays — no cudaMalloc anywhere)
__device__ float g_u0[CHW], g_u1[CHW], g_u2p[CHW], g_u3[CHW];  // u2 state (SoA)
__device__ float g_px[CHW], g_p0[CHW], g_p1[CHW];               // px, pr planes

__device__ __forceinline__ float4 ld4(const float* p) {
    return *reinterpret_cast<const float4*>(p);
}
__device__ __forceinline__ void st4(float* p, float a, float b, float c, float d) {
    *reinterpret_cast<float4*>(p) = make_float4(a, b, c, d);
}

// 2D tile mapping: block = 16 rows x 64 cols; thread (ti,tj) -> 4 pixels.
// 256 blocks/channel (32 i-tiles x 8 j-tiles), 768 blocks total.
__device__ __forceinline__ int tile_idx() {
    int tid = threadIdx.x;
    int bid = blockIdx.x;
    int c   = bid >> 8;
    int rem = bid & 255;
    int bi  = rem >> 3;
    int bj  = rem & 7;
    int gi  = bi * 16 + (tid >> 4);
    int gj  = bj * 64 + (tid & 15) * 4;
    return c * HW + gi * W + gj;
}

// ---------------------------------------------------------------------------
// Init: x2 = y, r2 = 0 (in d_out); SoA u planes = 0
// ---------------------------------------------------------------------------
__global__ __launch_bounds__(256) void k_init(const float* __restrict__ y,
                                              float* __restrict__ x2,
                                              float* __restrict__ r2f) {
    int t = blockIdx.x * blockDim.x + threadIdx.x;
    int idx = t * 4;
    *reinterpret_cast<float4*>(x2 + idx) = ld4(y + idx);
    st4(r2f + 2 * idx,     0.f, 0.f, 0.f, 0.f);
    st4(r2f + 2 * idx + 4, 0.f, 0.f, 0.f, 0.f);
    st4(g_u0 + idx, 0.f, 0.f, 0.f, 0.f);
    st4(g_u1 + idx, 0.f, 0.f, 0.f, 0.f);
    st4(g_u2p + idx, 0.f, 0.f, 0.f, 0.f);
    st4(g_u3 + idx, 0.f, 0.f, 0.f, 0.f);
}

// ---------------------------------------------------------------------------
// Phase A (fused tmp + xr): recompute tmp = TAU*epsilonT(u) at (i,j), (i-1,j),
// (i,j-1) from SoA u planes; then x/r prox + over-relax; write px, p0, p1.
// ---------------------------------------------------------------------------
__global__ __launch_bounds__(256) void k_A(float* __restrict__ x2,
                                           float* __restrict__ r2f,
                                           const float* __restrict__ y) {
    int idx = tile_idx();
    int j0 = idx & (W - 1);
    int i  = (idx >> 9) & (H - 1);
    bool up = (i >= 1), down = (i + 1 < H);
    bool rowlast = (j0 + 4 == W), rowfirst = (j0 == 0);

#if __CUDA_ARCH__ >= 900
    cudaGridDependencySynchronize();
#endif

    const float4 Z = make_float4(0, 0, 0, 0);
    float4 u0cv = ld4(g_u0 + idx);
    float4 u0uv = up   ? ld4(g_u0 + idx - W) : Z;
    float4 u0dv = down ? ld4(g_u0 + idx + W) : Z;
    float4 u1cv = ld4(g_u1 + idx);
    float4 u1uv = up ? ld4(g_u1 + idx - W) : Z;
    float  u1r  = rowlast ? 0.f : g_u1[idx + 4];
    float  u1ur = (up && !rowlast) ? g_u1[idx - W + 4] : 0.f;
    float4 u2cv = ld4(g_u2p + idx);
    float  u2l  = rowfirst ? 0.f : g_u2p[idx - 1];
    float  u2r  = rowlast  ? 0.f : g_u2p[idx + 4];
    float4 u3cv = ld4(g_u3 + idx);
    float4 u3uv = up ? ld4(g_u3 + idx - W) : Z;
    float  u3l  = rowfirst ? 0.f : g_u3[idx - 1];
    float  u3ul = (up && !rowfirst) ? g_u3[idx - W - 1] : 0.f;

    float u0c[4] = {u0cv.x, u0cv.y, u0cv.z, u0cv.w};
    float u0u[4] = {u0uv.x, u0uv.y, u0uv.z, u0uv.w};
    float u0d[4] = {u0dv.x, u0dv.y, u0dv.z, u0dv.w};
    float u1c[5] = {u1cv.x, u1cv.y, u1cv.z, u1cv.w, u1r};
    float u1u[5] = {u1uv.x, u1uv.y, u1uv.z, u1uv.w, u1ur};
    float u2w[6] = {u2l, u2cv.x, u2cv.y, u2cv.z, u2cv.w, u2r};   // [m] = col j0-1+m
    float u3w[5] = {u3l, u3cv.x, u3cv.y, u3cv.z, u3cv.w};        // [m] = col j0-1+m
    float u3uw[5]= {u3ul, u3uv.x, u3uv.y, u3uv.z, u3uv.w};

    float4 xo4 = ld4(x2 + idx);
    float4 y4  = ld4(y + idx);
    float4 rA  = ld4(r2f + 2 * idx);
    float4 rB  = ld4(r2f + 2 * idx + 4);
    float xoa[4] = {xo4.x, xo4.y, xo4.z, xo4.w};
    float ya[4]  = {y4.x, y4.y, y4.z, y4.w};
    float ro0[4] = {rA.x, rA.z, rB.x, rB.z};
    float ro1[4] = {rA.y, rA.w, rB.y, rB.w};

    float pxo[4], p0o[4], p1o[4], xno[4], rn0[4], rn1[4];
#pragma unroll
    for (int k = 0; k < 4; ++k) {
        bool lok = (k > 0) || !rowfirst;          // j >= 1
        bool rok = (k < 3) || !rowlast;           // j < W-1

        // tmp at (i,j)
        float t0c = TAU * (u0c[k] - (down ? u0d[k] : 0.f)
                           + (lok ? u1c[k] : 0.f) - (rok ? u1c[k + 1] : 0.f));
        float t1c = TAU * (u2w[k + 1] - (rok ? u2w[k + 2] : 0.f)
                           + (up ? u3uw[k + 1] : 0.f) - (down ? u3w[k + 1] : 0.f));
        // tmp0 at (i-1,j): a=i-1 always has a+1<=H-1
        float t0u = up ? TAU * (u0u[k] - u0c[k]
                                + (lok ? u1u[k] : 0.f) - (rok ? u1u[k + 1] : 0.f))
                       : 0.f;
        // tmp1 at (i,j-1): b=j-1 always has b+1<=W-1
        float t1l = lok ? TAU * (u2w[k] - u2w[k + 1]
                                 + (up ? u3uw[k] : 0.f) - (down ? u3w[k] : 0.f))
                        : 0.f;

        float dv = t0u - (down ? t0c : 0.f) + t1l - (rok ? t1c : 0.f);
        float x  = (xoa[k] - dv + TAU * ya[k]) * INV_1PT;

        float rr0 = ro0[k] + t0c;
        float rr1 = ro1[k] + t1c;
        float s   = rr0 * rr0 + rr1 * rr1;
        float im  = fminf(TAU_LAM1 * rsqrtf(s), 1.0f);
        float r0  = rr0 - rr0 * im;
        float r1  = rr1 - rr1 * im;

        pxo[k] = 2.0f * x - xoa[k];
        p0o[k] = 2.0f * r0 - ro0[k];
        p1o[k] = 2.0f * r1 - ro1[k];
        xno[k] = xoa[k] + RHO * (x - xoa[k]);
        rn0[k] = ro0[k] + RHO * (r0 - ro0[k]);
        rn1[k] = ro1[k] + RHO * (r1 - ro1[k]);
    }
    st4(g_px + idx, pxo[0], pxo[1], pxo[2], pxo[3]);
    st4(g_p0 + idx, p0o[0], p0o[1], p0o[2], p0o[3]);
    st4(g_p1 + idx, p1o[0], p1o[1], p1o[2], p1o[3]);
    st4(x2 + idx, xno[0], xno[1], xno[2], xno[3]);
    st4(r2f + 2 * idx,     rn0[0], rn1[0], rn0[1], rn1[1]);
    st4(r2f + 2 * idx + 4, rn0[2], rn1[2], rn0[3], rn1[3]);
}

// ---------------------------------------------------------------------------
// Phase B: q = nabla(px) - pr ; e = epsilon(q) ; u-prox + over-relax.
// Iterations write SoA planes; last iteration writes AoS float4 to d_out.
// ---------------------------------------------------------------------------
__global__ __launch_bounds__(256) void k_B(float4* __restrict__ u2out, int last) {
    int idx = tile_idx();
    int j0 = idx & (W - 1);
    int i  = (idx >> 9) & (H - 1);
    bool up = (i >= 1), down = (i + 1 < H);
    bool rowlast = (j0 + 4 == W), rowfirst = (j0 == 0);

#if __CUDA_ARCH__ >= 900
    cudaGridDependencySynchronize();
#endif

    float4 pxc = ld4(g_px + idx);
    float4 pxu = up   ? ld4(g_px + idx - W) : make_float4(0, 0, 0, 0);
    float4 pxd = down ? ld4(g_px + idx + W) : make_float4(0, 0, 0, 0);
    float pxl  = rowfirst ? 0.f : g_px[idx - 1];
    float pxr  = rowlast  ? 0.f : g_px[idx + 4];
    float pxdl = (down && !rowfirst) ? g_px[idx + W - 1] : 0.f;
    float pxdr = (down && !rowlast)  ? g_px[idx + W + 4] : 0.f;

    float4 p0c = ld4(g_p0 + idx);
    float4 p0u = up ? ld4(g_p0 + idx - W) : make_float4(0, 0, 0, 0);
    float  p0l = rowfirst ? 0.f : g_p0[idx - 1];
    float4 p1c = ld4(g_p1 + idx);
    float  p1l = rowfirst ? 0.f : g_p1[idx - 1];
    float4 p1d = down ? ld4(g_p1 + idx + W) : make_float4(0, 0, 0, 0);

    float pxa[6]  = {pxl, pxc.x, pxc.y, pxc.z, pxc.w, pxr};      // [k+1] = j
    float pxda[6] = {pxdl, pxd.x, pxd.y, pxd.z, pxd.w, pxdr};
    float pxua[4] = {pxu.x, pxu.y, pxu.z, pxu.w};
    float p0w[5]  = {p0l, p0c.x, p0c.y, p0c.z, p0c.w};           // [k] = j-1
    float p0ua[4] = {p0u.x, p0u.y, p0u.z, p0u.w};
    float p1w[5]  = {p1l, p1c.x, p1c.y, p1c.z, p1c.w};
    float p1da[4] = {p1d.x, p1d.y, p1d.z, p1d.w};

    float4 u0c = ld4(g_u0 + idx);
    float4 u1c = ld4(g_u1 + idx);
    float4 u2c = ld4(g_u2p + idx);
    float4 u3c = ld4(g_u3 + idx);
    float uo0[4] = {u0c.x, u0c.y, u0c.z, u0c.w};
    float uo1[4] = {u1c.x, u1c.y, u1c.z, u1c.w};
    float uo2[4] = {u2c.x, u2c.y, u2c.z, u2c.w};
    float uo3[4] = {u3c.x, u3c.y, u3c.z, u3c.w};

    float nu0[4], nu1[4], nu2[4], nu3[4];
#pragma unroll
    for (int k = 0; k < 4; ++k) {
        int kc = k + 1;
        bool lok = (k > 0) || !rowfirst;
        bool rok = (k < 3) || !rowlast;

        float q0c = (down ? (pxda[kc] - pxa[kc]) : 0.f) - p0w[k + 1];
        float q0u = up  ? ((pxa[kc] - pxua[k]) - p0ua[k]) : 0.f;
        float q0l = lok ? ((down ? (pxda[kc - 1] - pxa[kc - 1]) : 0.f) - p0w[k]) : 0.f;
        float q1c = (rok ? (pxa[kc + 1] - pxa[kc]) : 0.f) - p1w[k + 1];
        float q1l = lok ? ((pxa[kc] - pxa[kc - 1]) - p1w[k]) : 0.f;
        float q1d = down ? ((rok ? (pxda[kc + 1] - pxda[kc]) : 0.f) - p1da[k]) : 0.f;

        float e0 = q0c - q0u;
        float e1 = lok ? (q0c - q0l) : 0.f;
        float e2 = q1c - q1l;
        float e3 = down ? (q1d - q1c) : 0.f;

        float un0 = uo0[k] + SIGMA * e0;
        float un1 = uo1[k] + SIGMA * e1;
        float un2 = uo2[k] + SIGMA * e2;
        float un3 = uo3[k] + SIGMA * e3;

        float s  = un0 * un0 + un1 * un1 + un2 * un2 + un3 * un3;
        float im = fminf(LAM2 * rsqrtf(s), 1.0f);

        nu0[k] = uo0[k] + RHO * (un0 * im - uo0[k]);
        nu1[k] = uo1[k] + RHO * (un1 * im - uo1[k]);
        nu2[k] = uo2[k] + RHO * (un2 * im - uo2[k]);
        nu3[k] = uo3[k] + RHO * (un3 * im - uo3[k]);
    }

    if (last) {
#pragma unroll
        for (int k = 0; k < 4; ++k)
            u2out[idx + k] = make_float4(nu0[k], nu1[k], nu2[k], nu3[k]);
    } else {
        st4(g_u0 + idx, nu0[0], nu0[1], nu0[2], nu0[3]);
        st4(g_u1 + idx, nu1[0], nu1[1], nu1[2], nu1[3]);
        st4(g_u2p + idx, nu2[0], nu2[1], nu2[2], nu2[3]);
        st4(g_u3 + idx, nu3[0], nu3[1], nu3[2], nu3[3]);
    }
}

// ---------------------------------------------------------------------------
// PDL launches: next kernel's prologue overlaps previous kernel's tail;
// cudaGridDependencySynchronize() enforces the data dependency.
// ---------------------------------------------------------------------------
template <typename... Args>
static inline void launch_pdl(void (*kern)(Args...), int blocks, int threads,
                              Args... args) {
    cudaLaunchConfig_t cfg = {};
    cfg.gridDim  = dim3(blocks);
    cfg.blockDim = dim3(threads);
    cfg.stream   = 0;
    cudaLaunchAttribute attr[1];
    attr[0].id = cudaLaunchAttributeProgrammaticStreamSerialization;
    attr[0].val.programmaticStreamSerializationAllowed = 1;
    cfg.attrs = attr;
    cfg.numAttrs = 1;
    cudaLaunchKernelEx(&cfg, kern, args...);
}

extern "C" void kernel_launch(void* const* d_in, const int* in_sizes, int n_in,
                              void* d_out, int out_size) {
    const float* y = (const float*)d_in[0];
    float*  out = (float*)d_out;
    float*  x2  = out;
    float*  r2f = out + CHW;
    float4* u2o = (float4*)(out + 3 * CHW);

    const int threads = 256;
    const int blocks  = 768;   // 32 i-tiles x 8 j-tiles x 3 channels

    k_init<<<blocks, threads>>>(y, x2, r2f);
    for (int it = 0; it < N_IT; ++it) {
        launch_pdl(k_A, blocks, threads, x2, r2f, (const float*)y);
        launch_pdl(k_B, blocks, threads, u2o, it == N_IT - 1 ? 1 : 0);
    }
}